// round 5
// baseline (speedup 1.0000x reference)
#include <cuda_runtime.h>
#include <cuda_bf16.h>

// Problem: out[i] = mean_{p != i} ( tanh( [x_i, x_p] @ W1 + b1 ) @ W2 + b2 )
// Restructured: A = x@W1[:64] + b1, B = x@W1[64:]
//   out[i] = ( (sum_p tanh(A[i]+B[p]) - tanh(A[i]+B[i])) / 1023 ) @ W2 + b2

#define N_E    1024
#define N_IN   64
#define HIDDEN 128
#define OUTD   64
#define PSPLIT 4
#define PCHUNK (N_E / PSPLIT)   // 256
#define TI     8                // i-rows per block in phase 2
#define TI1    8                // i-rows per block in phase 1

// Scratch (device globals — no runtime allocation allowed)
__device__ float g_A[N_E * HIDDEN];                   // 512 KB
__device__ float g_B[N_E * HIDDEN];                   // 512 KB
__device__ float g_Sp[PSPLIT * N_E * HIDDEN];         // 2 MB partial sums

__device__ __forceinline__ float tanh_fast(float x) {
    float y;
    asm("tanh.approx.f32 %0, %1;" : "=f"(y) : "f"(x));
    return y;
}

// ---------------------------------------------------------------------------
// Phase 1: A[i,h] = b1[h] + sum_f x[i,f]*W1[f,h];  B[i,h] = sum_f x[i,f]*W1[64+f,h]
// 128 blocks x 128 threads; each block handles TI1=8 rows of x, reusing W1 loads.
// ---------------------------------------------------------------------------
__global__ void __launch_bounds__(HIDDEN) phase1_kernel(
    const float* __restrict__ x, const float* __restrict__ W1,
    const float* __restrict__ b1)
{
    const int h  = threadIdx.x;           // hidden index 0..127
    const int i0 = blockIdx.x * TI1;

    __shared__ float xs[TI1][N_IN];
    #pragma unroll
    for (int q = 0; q < (TI1 * N_IN) / HIDDEN; q++) {
        int idx = q * HIDDEN + h;         // 0..511
        xs[idx >> 6][idx & 63] = x[i0 * N_IN + idx];
    }
    __syncthreads();

    float a[TI1], b[TI1];
    const float bb = b1[h];
    #pragma unroll
    for (int k = 0; k < TI1; k++) { a[k] = bb; b[k] = 0.0f; }

    #pragma unroll 4
    for (int f = 0; f < N_IN; f++) {
        const float wa = W1[f * HIDDEN + h];
        const float wb = W1[(N_IN + f) * HIDDEN + h];
        #pragma unroll
        for (int k = 0; k < TI1; k++) {
            const float xv = xs[k][f];
            a[k] = fmaf(xv, wa, a[k]);
            b[k] = fmaf(xv, wb, b[k]);
        }
    }

    #pragma unroll
    for (int k = 0; k < TI1; k++) {
        g_A[(i0 + k) * HIDDEN + h] = a[k];
        g_B[(i0 + k) * HIDDEN + h] = b[k];
    }
}

// ---------------------------------------------------------------------------
// Phase 2 (dominant, MUFU-bound): partial sums of tanh(A[i]+B[p]) over p-chunks.
// Grid (128 i-tiles, 4 p-chunks) = 512 CTAs of 128 threads. Thread = hidden h.
// 8 independent accumulators/thread for MUFU-latency hiding.
// ---------------------------------------------------------------------------
__global__ void __launch_bounds__(HIDDEN) phase2_kernel()
{
    const int h  = threadIdx.x;
    const int i0 = blockIdx.x * TI;
    const int pc = blockIdx.y;
    const int p0 = pc * PCHUNK;

    float a[TI], acc[TI];
    #pragma unroll
    for (int k = 0; k < TI; k++) {
        a[k]   = g_A[(i0 + k) * HIDDEN + h];
        acc[k] = 0.0f;
    }

    const float* __restrict__ Bp = &g_B[p0 * HIDDEN + h];
    #pragma unroll 4
    for (int p = 0; p < PCHUNK; p++) {
        const float bp = Bp[p * HIDDEN];
        #pragma unroll
        for (int k = 0; k < TI; k++) {
            acc[k] += tanh_fast(a[k] + bp);
        }
    }

    float* __restrict__ Sp = &g_Sp[(pc * N_E + i0) * HIDDEN + h];
    #pragma unroll
    for (int k = 0; k < TI; k++) Sp[k * HIDDEN] = acc[k];
}

// ---------------------------------------------------------------------------
// Phase 3: reduce partials, remove self term, scale, project through W2, add b2.
// One block per entity i; 128 threads (first 128 build s[], first 64 do GEMV).
// ---------------------------------------------------------------------------
__global__ void __launch_bounds__(HIDDEN) phase3_kernel(
    const float* __restrict__ W2, const float* __restrict__ b2,
    float* __restrict__ out)
{
    const int i = blockIdx.x;
    const int t = threadIdx.x;

    __shared__ float s[HIDDEN];

    float v = 0.0f;
    #pragma unroll
    for (int c = 0; c < PSPLIT; c++)
        v += g_Sp[(c * N_E + i) * HIDDEN + t];

    // self term: partner list excludes p == i
    const float self_t = tanh_fast(g_A[i * HIDDEN + t] + g_B[i * HIDDEN + t]);
    s[t] = (v - self_t) * (1.0f / (float)(N_E - 1));
    __syncthreads();

    if (t < OUTD) {
        float o = b2[t];
        #pragma unroll 8
        for (int hh = 0; hh < HIDDEN; hh++)
            o = fmaf(s[hh], W2[hh * OUTD + t], o);
        out[i * OUTD + t] = o;
    }
}

// ---------------------------------------------------------------------------
extern "C" void kernel_launch(void* const* d_in, const int* in_sizes, int n_in,
                              void* d_out, int out_size)
{
    // Map inputs by element count (all distinct): x=65536, W1=16384, b1=128,
    // W2=8192, b2=64.
    const float *x = nullptr, *W1 = nullptr, *b1 = nullptr, *W2 = nullptr, *b2 = nullptr;
    for (int i = 0; i < n_in; i++) {
        switch (in_sizes[i]) {
            case N_E * N_IN:          x  = (const float*)d_in[i]; break; // 65536
            case 2 * N_IN * HIDDEN:   W1 = (const float*)d_in[i]; break; // 16384
            case HIDDEN:              b1 = (const float*)d_in[i]; break; // 128
            case HIDDEN * OUTD:       W2 = (const float*)d_in[i]; break; // 8192
            case OUTD:                b2 = (const float*)d_in[i]; break; // 64
            default: break;
        }
    }
    float* out = (float*)d_out;

    phase1_kernel<<<N_E / TI1, HIDDEN>>>(x, W1, b1);

    dim3 g2(N_E / TI, PSPLIT);
    phase2_kernel<<<g2, HIDDEN>>>();

    phase3_kernel<<<N_E, HIDDEN>>>(W2, b2, out);
}

// round 6
// speedup vs baseline: 1.2500x; 1.2500x over previous
#include <cuda_runtime.h>
#include <cuda_bf16.h>

// Problem: out[i] = mean_{p != i} ( tanh( [x_i, x_p] @ W1 + b1 ) @ W2 + b2 )
// Restructured: A = x@W1[:64] + b1, B = x@W1[64:]
//   out[i] = ( (sum_p tanh(A[i]+B[p]) - tanh(A[i]+B[i])) / 1023 ) @ W2 + b2

#define N_E    1024
#define N_IN   64
#define HIDDEN 128
#define OUTD   64
#define PSPLIT 8
#define PCHUNK (N_E / PSPLIT)   // 128
#define TI     8                // i-rows per block in phase 2
#define TI1    2                // i-rows per block in phase 1 (occupancy fix)

// Scratch (device globals — no runtime allocation allowed)
__device__ float g_A[N_E * HIDDEN];                   // 512 KB
__device__ float g_B[N_E * HIDDEN];                   // 512 KB
__device__ float g_Sp[PSPLIT * N_E * HIDDEN];         // 4 MB partial sums

__device__ __forceinline__ float tanh_fast(float x) {
    float y;
    asm("tanh.approx.f32 %0, %1;" : "=f"(y) : "f"(x));
    return y;
}

// ---------------------------------------------------------------------------
// Phase 1: A[i,h] = b1[h] + sum_f x[i,f]*W1[f,h];  B[i,h] = sum_f x[i,f]*W1[64+f,h]
// 512 blocks x 128 threads, TI1=2 rows each -> ~14 warps/SM (was 4), so the
// 64-deep chain of W1 L2 loads is latency-hidden by other warps.
// ---------------------------------------------------------------------------
__global__ void __launch_bounds__(HIDDEN) phase1_kernel(
    const float* __restrict__ x, const float* __restrict__ W1,
    const float* __restrict__ b1)
{
    const int h  = threadIdx.x;           // hidden index 0..127
    const int i0 = blockIdx.x * TI1;

    __shared__ float xs[TI1][N_IN];
    {
        int idx = h;                      // 0..127 covers TI1*N_IN = 128 elems
        xs[idx >> 6][idx & 63] = x[i0 * N_IN + idx];
    }
    __syncthreads();

    float a[TI1], b[TI1];
    const float bb = b1[h];
    #pragma unroll
    for (int k = 0; k < TI1; k++) { a[k] = bb; b[k] = 0.0f; }

    #pragma unroll 8
    for (int f = 0; f < N_IN; f++) {
        const float wa = W1[f * HIDDEN + h];
        const float wb = W1[(N_IN + f) * HIDDEN + h];
        #pragma unroll
        for (int k = 0; k < TI1; k++) {
            const float xv = xs[k][f];
            a[k] = fmaf(xv, wa, a[k]);
            b[k] = fmaf(xv, wb, b[k]);
        }
    }

    #pragma unroll
    for (int k = 0; k < TI1; k++) {
        g_A[(i0 + k) * HIDDEN + h] = a[k];
        g_B[(i0 + k) * HIDDEN + h] = b[k];
    }
}

// ---------------------------------------------------------------------------
// Phase 2 (dominant, MUFU-bound): partial sums of tanh(A[i]+B[p]) over p-chunks.
// Grid (128 i-tiles, 8 p-chunks) = 1024 CTAs of 128 threads (~7 CTAs/SM).
// Thread = hidden h; 8 independent accumulators/thread hide MUFU latency.
// ---------------------------------------------------------------------------
__global__ void __launch_bounds__(HIDDEN) phase2_kernel()
{
    const int h  = threadIdx.x;
    const int i0 = blockIdx.x * TI;
    const int pc = blockIdx.y;
    const int p0 = pc * PCHUNK;

    float a[TI], acc[TI];
    #pragma unroll
    for (int k = 0; k < TI; k++) {
        a[k]   = g_A[(i0 + k) * HIDDEN + h];
        acc[k] = 0.0f;
    }

    const float* __restrict__ Bp = &g_B[p0 * HIDDEN + h];
    #pragma unroll 4
    for (int p = 0; p < PCHUNK; p++) {
        const float bp = Bp[p * HIDDEN];
        #pragma unroll
        for (int k = 0; k < TI; k++) {
            acc[k] += tanh_fast(a[k] + bp);
        }
    }

    float* __restrict__ Sp = &g_Sp[(pc * N_E + i0) * HIDDEN + h];
    #pragma unroll
    for (int k = 0; k < TI; k++) Sp[k * HIDDEN] = acc[k];
}

// ---------------------------------------------------------------------------
// Phase 3: reduce partials, remove self term, scale, project through W2, add b2.
// One block per entity i; all 128 threads participate in the GEMV
// (hidden dim split in two halves, pair-reduced in shared).
// ---------------------------------------------------------------------------
__global__ void __launch_bounds__(HIDDEN) phase3_kernel(
    const float* __restrict__ W2, const float* __restrict__ b2,
    float* __restrict__ out)
{
    const int i = blockIdx.x;
    const int t = threadIdx.x;

    __shared__ float s[HIDDEN];
    __shared__ float po[2][OUTD];

    float v = 0.0f;
    #pragma unroll
    for (int c = 0; c < PSPLIT; c++)
        v += g_Sp[(c * N_E + i) * HIDDEN + t];

    // self term: partner list excludes p == i
    const float self_t = tanh_fast(g_A[i * HIDDEN + t] + g_B[i * HIDDEN + t]);
    s[t] = (v - self_t) * (1.0f / (float)(N_E - 1));
    __syncthreads();

    const int o    = t & (OUTD - 1);   // output index 0..63
    const int half = t >> 6;           // which half of hidden
    float acc = 0.0f;
    #pragma unroll 16
    for (int hh = 0; hh < HIDDEN / 2; hh++) {
        const int hid = half * (HIDDEN / 2) + hh;
        acc = fmaf(s[hid], W2[hid * OUTD + o], acc);
    }
    po[half][o] = acc;
    __syncthreads();

    if (t < OUTD)
        out[i * OUTD + t] = po[0][t] + po[1][t] + b2[t];
}

// ---------------------------------------------------------------------------
extern "C" void kernel_launch(void* const* d_in, const int* in_sizes, int n_in,
                              void* d_out, int out_size)
{
    // Map inputs by element count (all distinct): x=65536, W1=16384, b1=128,
    // W2=8192, b2=64.
    const float *x = nullptr, *W1 = nullptr, *b1 = nullptr, *W2 = nullptr, *b2 = nullptr;
    for (int i = 0; i < n_in; i++) {
        switch (in_sizes[i]) {
            case N_E * N_IN:          x  = (const float*)d_in[i]; break; // 65536
            case 2 * N_IN * HIDDEN:   W1 = (const float*)d_in[i]; break; // 16384
            case HIDDEN:              b1 = (const float*)d_in[i]; break; // 128
            case HIDDEN * OUTD:       W2 = (const float*)d_in[i]; break; // 8192
            case OUTD:                b2 = (const float*)d_in[i]; break; // 64
            default: break;
        }
    }
    float* out = (float*)d_out;

    phase1_kernel<<<N_E / TI1, HIDDEN>>>(x, W1, b1);

    dim3 g2(N_E / TI, PSPLIT);
    phase2_kernel<<<g2, HIDDEN>>>();

    phase3_kernel<<<N_E, HIDDEN>>>(W2, b2, out);
}